// round 1
// baseline (speedup 1.0000x reference)
#include <cuda_runtime.h>
#include <math.h>

#define BATCH 8
#define NPTS  8192
#define TOTAL (BATCH * NPTS)
#define TILE  1024
#define EPSF  1e-10f

// Scratch in __device__ globals (no allocation allowed).
__device__ float4 g_xp[TOTAL];
__device__ float4 g_yp[TOTAL];
__device__ float  g_min1[TOTAL];   // per x-point: min_m (yy - 2*dot)  (+xx added)
__device__ float  g_min2[TOTAL];   // per y-point: min_n (xx - 2*dot)  (+yy added)
__device__ float  g_batch[BATCH];

// ---------------------------------------------------------------------------
// Pack (B,N,3) coords into float4 {p0,p1,p2, |p|^2}
// ---------------------------------------------------------------------------
__global__ void pack_kernel(const float* __restrict__ x,
                            const float* __restrict__ y) {
    int n = blockIdx.x * blockDim.x + threadIdx.x;
    if (n >= TOTAL) return;
    float x0 = x[3 * n + 0], x1 = x[3 * n + 1], x2 = x[3 * n + 2];
    g_xp[n] = make_float4(x0, x1, x2, fmaf(x0, x0, fmaf(x1, x1, x2 * x2)));
    float y0 = y[3 * n + 0], y1 = y[3 * n + 1], y2 = y[3 * n + 2];
    g_yp[n] = make_float4(y0, y1, y2, fmaf(y0, y0, fmaf(y1, y1, y2 * y2)));
}

// ---------------------------------------------------------------------------
// Min pass: each thread owns one A-point, scans all B-points of its batch
// through a shared-memory tile. Per pair: 3 FMA + 1 FMNMX.
//   s = (-2a0)*p0 + (-2a1)*p1 + (-2a2)*p2 + |p|^2  == |p|^2 - 2<a,p>
//   d2min = |a|^2 + min_p s
// PASS=0: A=x, B=y -> g_min1 ; PASS=1: A=y, B=x -> g_min2
// ---------------------------------------------------------------------------
template <int PASS>
__global__ void __launch_bounds__(256) minpass_kernel() {
    const float4* __restrict__ A  = (PASS == 0) ? g_xp : g_yp;
    const float4* __restrict__ Bp = (PASS == 0) ? g_yp : g_xp;
    float* __restrict__ out       = (PASS == 0) ? g_min1 : g_min2;

    __shared__ float4 sb[TILE];

    int n = blockIdx.x * 256 + threadIdx.x;   // 256 blocks x 256 thr = 65536
    int b = n >> 13;                          // batch (block-uniform: 8192%256==0)

    float4 a = A[n];
    float n20 = -2.0f * a.x, n21 = -2.0f * a.y, n22 = -2.0f * a.z;

    float m0 = 1e30f, m1 = 1e30f, m2 = 1e30f, m3 = 1e30f;

    const float4* base = Bp + b * NPTS;
    for (int t = 0; t < NPTS; t += TILE) {
        #pragma unroll
        for (int i = 0; i < TILE / 256; i++)
            sb[threadIdx.x + i * 256] = base[t + threadIdx.x + i * 256];
        __syncthreads();

        #pragma unroll 4
        for (int j = 0; j < TILE; j += 4) {
            float4 p0 = sb[j + 0];
            float4 p1 = sb[j + 1];
            float4 p2 = sb[j + 2];
            float4 p3 = sb[j + 3];
            m0 = fminf(m0, fmaf(n20, p0.x, fmaf(n21, p0.y, fmaf(n22, p0.z, p0.w))));
            m1 = fminf(m1, fmaf(n20, p1.x, fmaf(n21, p1.y, fmaf(n22, p1.z, p1.w))));
            m2 = fminf(m2, fmaf(n20, p2.x, fmaf(n21, p2.y, fmaf(n22, p2.z, p2.w))));
            m3 = fminf(m3, fmaf(n20, p3.x, fmaf(n21, p3.y, fmaf(n22, p3.z, p3.w))));
        }
        __syncthreads();
    }
    out[n] = a.w + fminf(fminf(m0, m1), fminf(m2, m3));
}

// ---------------------------------------------------------------------------
// Per-batch: mean over sqrt(min+EPS) both directions, take max.
// Deterministic tree reduction (no float atomics).
// ---------------------------------------------------------------------------
__global__ void __launch_bounds__(256) reduce_kernel() {
    int b   = blockIdx.x;
    int tid = threadIdx.x;
    __shared__ float s1[256], s2[256];

    float acc1 = 0.0f, acc2 = 0.0f;
    for (int i = tid; i < NPTS; i += 256) {
        acc1 += sqrtf(g_min1[b * NPTS + i] + EPSF);
        acc2 += sqrtf(g_min2[b * NPTS + i] + EPSF);
    }
    s1[tid] = acc1;
    s2[tid] = acc2;
    __syncthreads();
    for (int s = 128; s > 0; s >>= 1) {
        if (tid < s) {
            s1[tid] += s1[tid + s];
            s2[tid] += s2[tid + s];
        }
        __syncthreads();
    }
    if (tid == 0)
        g_batch[b] = fmaxf(s1[0], s2[0]) * (1.0f / NPTS);
}

__global__ void final_kernel(float* __restrict__ out) {
    float s = 0.0f;
    #pragma unroll
    for (int b = 0; b < BATCH; b++) s += g_batch[b];
    out[0] = s;
}

// ---------------------------------------------------------------------------
extern "C" void kernel_launch(void* const* d_in, const int* in_sizes, int n_in,
                              void* d_out, int out_size) {
    const float* x = (const float*)d_in[0];
    const float* y = (const float*)d_in[1];
    float* out = (float*)d_out;

    pack_kernel<<<TOTAL / 256, 256>>>(x, y);
    minpass_kernel<0><<<TOTAL / 256, 256>>>();
    minpass_kernel<1><<<TOTAL / 256, 256>>>();
    reduce_kernel<<<BATCH, 256>>>();
    final_kernel<<<1, 1>>>(out);
}

// round 2
// speedup vs baseline: 1.4826x; 1.4826x over previous
#include <cuda_runtime.h>
#include <math.h>

#define BATCH 8
#define NPTS  8192
#define TOTAL (BATCH * NPTS)
#define TILE  1024                      // B-points per smem tile
#define TPB   128                       // threads per minpass block
#define APB   256                       // A-points per block (2 per thread)
#define BLKS_PER_PASS (TOTAL / APB)     // 256
#define EPSF  1e-10f

typedef unsigned long long u64;

// Scratch (__device__ globals; no allocation allowed).
__device__ float4 g_xp[TOTAL];          // x points as {x,y,z,|p|^2}
__device__ float4 g_yp[TOTAL];
__device__ float  g_t0[TOTAL * 4];      // pair-transposed y  (B-side of pass 0)
__device__ float  g_t1[TOTAL * 4];      // pair-transposed x  (B-side of pass 1)
__device__ float  g_part[2 * BLKS_PER_PASS];

// ---------------------------------------------------------------------------
// f32x2 helpers
// ---------------------------------------------------------------------------
__device__ __forceinline__ u64 pack2(float lo, float hi) {
    u64 r;
    asm("mov.b64 %0, {%1, %2};" : "=l"(r) : "f"(lo), "f"(hi));
    return r;
}

// m{lo,hi} = min(m{lo,hi}, nx*bx + ny*by + nz*bz + w), elementwise over the
// two B-points packed in bx/by/bz/bw. 3x FFMA2 (fma pipe) + 2x FMNMX (alu pipe).
__device__ __forceinline__ void body(float& mlo, float& mhi,
                                     u64 nx, u64 ny, u64 nz,
                                     u64 bx, u64 by, u64 bz, u64 bw) {
    asm("{\n\t"
        ".reg .b64 t;\n\t"
        ".reg .f32 slo, shi;\n\t"
        "fma.rn.f32x2 t, %4, %7, %8;\n\t"   // nz*bz + w
        "fma.rn.f32x2 t, %3, %6, t;\n\t"    // + ny*by
        "fma.rn.f32x2 t, %2, %5, t;\n\t"    // + nx*bx
        "mov.b64 {slo, shi}, t;\n\t"
        "min.f32 %0, %0, slo;\n\t"
        "min.f32 %1, %1, shi;\n\t"
        "}"
        : "+f"(mlo), "+f"(mhi)
        : "l"(nx), "l"(ny), "l"(nz), "l"(bx), "l"(by), "l"(bz), "l"(bw));
}

// ---------------------------------------------------------------------------
// Pack: build float4 point arrays + pair-transposed B-side arrays.
// Pair j = points (2j, 2j+1); layout per pair: {x0,x1, y0,y1, z0,z1, w0,w1}.
// ---------------------------------------------------------------------------
__global__ void pack_kernel(const float* __restrict__ x,
                            const float* __restrict__ y) {
    int j = blockIdx.x * blockDim.x + threadIdx.x;
    if (j >= TOTAL / 2) return;
    int n0 = 2 * j, n1 = 2 * j + 1;

    {   // x side -> g_xp (A of pass 0), g_t1 (B of pass 1)
        float a0 = x[3 * n0], a1 = x[3 * n0 + 1], a2 = x[3 * n0 + 2];
        float b0 = x[3 * n1], b1 = x[3 * n1 + 1], b2 = x[3 * n1 + 2];
        float wa = fmaf(a0, a0, fmaf(a1, a1, a2 * a2));
        float wb = fmaf(b0, b0, fmaf(b1, b1, b2 * b2));
        g_xp[n0] = make_float4(a0, a1, a2, wa);
        g_xp[n1] = make_float4(b0, b1, b2, wb);
        float4* t = (float4*)(g_t1 + 8 * (size_t)j);
        t[0] = make_float4(a0, b0, a1, b1);
        t[1] = make_float4(a2, b2, wa, wb);
    }
    {   // y side -> g_yp (A of pass 1), g_t0 (B of pass 0)
        float a0 = y[3 * n0], a1 = y[3 * n0 + 1], a2 = y[3 * n0 + 2];
        float b0 = y[3 * n1], b1 = y[3 * n1 + 1], b2 = y[3 * n1 + 2];
        float wa = fmaf(a0, a0, fmaf(a1, a1, a2 * a2));
        float wb = fmaf(b0, b0, fmaf(b1, b1, b2 * b2));
        g_yp[n0] = make_float4(a0, a1, a2, wa);
        g_yp[n1] = make_float4(b0, b1, b2, wb);
        float4* t = (float4*)(g_t0 + 8 * (size_t)j);
        t[0] = make_float4(a0, b0, a1, b1);
        t[1] = make_float4(a2, b2, wa, wb);
    }
}

// ---------------------------------------------------------------------------
// Fused min pass (both directions, one 512-block launch).
// Block blk: pass = blk>>8, pb = blk&255, covers A-points [pb*256, pb*256+256)
// with 2 A-points per thread. Scans all 8192 B-points of the batch through a
// pair-transposed smem tile. Per (2A x 2B) iter: 6 FFMA2 + 4 FMNMX + 2
// broadcast LDS.128 -> fma-pipe bound at 3 cyc per 128 pair-evals per SM.
// Epilogue: sqrt + block-sum -> one partial per block (kills reduce_kernel).
// ---------------------------------------------------------------------------
__global__ void __launch_bounds__(TPB) minpass_kernel() {
    const int blk  = blockIdx.x;
    const int pass = blk >> 8;
    const int pb   = blk & (BLKS_PER_PASS - 1);
    const int tid  = threadIdx.x;

    const float4* __restrict__ A = pass ? g_yp : g_xp;
    const float*  __restrict__ T = pass ? g_t1 : g_t0;

    const int aBase = pb * APB;
    const int batch = aBase >> 13;          // /8192 (uniform within block)

    __shared__ ulonglong2 sb[TILE];         // TILE B-points * 16B = 16 KB
    __shared__ float red[TPB];

    float4 a0 = A[aBase + tid];
    float4 a1 = A[aBase + tid + TPB];
    const u64 nx0 = pack2(-2.0f * a0.x, -2.0f * a0.x);
    const u64 ny0 = pack2(-2.0f * a0.y, -2.0f * a0.y);
    const u64 nz0 = pack2(-2.0f * a0.z, -2.0f * a0.z);
    const u64 nx1 = pack2(-2.0f * a1.x, -2.0f * a1.x);
    const u64 ny1 = pack2(-2.0f * a1.y, -2.0f * a1.y);
    const u64 nz1 = pack2(-2.0f * a1.z, -2.0f * a1.z);

    float m0l = 1e30f, m0h = 1e30f, m1l = 1e30f, m1h = 1e30f;

    for (int t0 = 0; t0 < NPTS; t0 += TILE) {
        const ulonglong2* src =
            (const ulonglong2*)(T + 4 * (size_t)(batch * NPTS + t0));
        #pragma unroll
        for (int i = 0; i < TILE / TPB; i++)
            sb[tid + i * TPB] = src[tid + i * TPB];
        __syncthreads();

        #pragma unroll 8
        for (int p = 0; p < TILE / 2; p++) {
            ulonglong2 q0 = sb[2 * p + 0];   // {x0x1, y0y1}
            ulonglong2 q1 = sb[2 * p + 1];   // {z0z1, w0w1}
            body(m0l, m0h, nx0, ny0, nz0, q0.x, q0.y, q1.x, q1.y);
            body(m1l, m1h, nx1, ny1, nz1, q0.x, q0.y, q1.x, q1.y);
        }
        __syncthreads();
    }

    float d = sqrtf(a0.w + fminf(m0l, m0h) + EPSF) +
              sqrtf(a1.w + fminf(m1l, m1h) + EPSF);

    red[tid] = d;
    __syncthreads();
    #pragma unroll
    for (int s = TPB / 2; s > 0; s >>= 1) {
        if (tid < s) red[tid] += red[tid + s];
        __syncthreads();
    }
    if (tid == 0) g_part[blk] = red[0];
}

// ---------------------------------------------------------------------------
// Final: fold 2*256 partials -> per-batch means -> max -> sum.
// Warp w handles batch w (blocks pb in [w*32, w*32+32) are exactly batch w).
// ---------------------------------------------------------------------------
__global__ void __launch_bounds__(256) final_kernel(float* __restrict__ out) {
    const int w = threadIdx.x >> 5, lane = threadIdx.x & 31;
    __shared__ float bs[BATCH];

    float s1 = g_part[w * 32 + lane];
    float s2 = g_part[BLKS_PER_PASS + w * 32 + lane];
    #pragma unroll
    for (int o = 16; o > 0; o >>= 1) {
        s1 += __shfl_down_sync(0xffffffffu, s1, o);
        s2 += __shfl_down_sync(0xffffffffu, s2, o);
    }
    if (lane == 0) bs[w] = fmaxf(s1, s2) * (1.0f / NPTS);
    __syncthreads();
    if (threadIdx.x == 0) {
        float s = 0.0f;
        #pragma unroll
        for (int b = 0; b < BATCH; b++) s += bs[b];
        out[0] = s;
    }
}

// ---------------------------------------------------------------------------
extern "C" void kernel_launch(void* const* d_in, const int* in_sizes, int n_in,
                              void* d_out, int out_size) {
    const float* x = (const float*)d_in[0];
    const float* y = (const float*)d_in[1];
    float* out = (float*)d_out;

    pack_kernel<<<(TOTAL / 2 + 255) / 256, 256>>>(x, y);
    minpass_kernel<<<2 * BLKS_PER_PASS, TPB>>>();
    final_kernel<<<1, 256>>>(out);
}

// round 3
// speedup vs baseline: 1.6256x; 1.0964x over previous
#include <cuda_runtime.h>
#include <math.h>

#define BATCH 8
#define NPTS  8192
#define NSLOT 16                     // 8 batches x 2 clouds
#define TOTPTS (NSLOT * NPTS)        // 131072
#define G 32
#define NC (G * G * G)               // 32768 cells per grid
#define NCT (NSLOT * NC)             // 524288 cells total
#define LOB  (-5.5f)
#define HCELL (11.0f / G)
#define INVH  (G / 11.0f)
#define EPSF 1e-10f

// ---- static scratch (no allocation allowed) -------------------------------
__device__ float4 g_pk[TOTPTS];      // packed points, original order, per slot
__device__ float4 g_sorted[TOTPTS];  // points sorted by cell (global CSR)
__device__ int    g_cell[TOTPTS];    // flat cell id per point
__device__ int    g_cnt[NCT];        // per-cell counts
__device__ int    g_start[NCT + 1];  // CSR starts (exclusive scan) + sentinel
__device__ int    g_cursor[NCT];     // scatter cursors
__device__ int    g_bsum[512];
__device__ int    g_boff[512];
__device__ float  g_part[512];       // per-block partial sums of sqrt(min)

// ---------------------------------------------------------------------------
__global__ void zero_kernel() {
    int i = blockIdx.x * 1024 + threadIdx.x;
    if (i < NCT) g_cnt[i] = 0;
}

// Pack points, compute cells, histogram.
// t in [0,131072): slot = t>>13 (b*2 + side), i = t&8191. side0=x, side1=y.
__global__ void assign_kernel(const float* __restrict__ x,
                              const float* __restrict__ y) {
    int t = blockIdx.x * 256 + threadIdx.x;
    int slot = t >> 13, i = t & (NPTS - 1);
    int b = slot >> 1;
    const float* src = (slot & 1) ? y : x;
    const float* p = src + ((size_t)b * NPTS + i) * 3;
    float px = p[0], py = p[1], pz = p[2];
    int cx = min(G - 1, max(0, (int)((px - LOB) * INVH)));
    int cy = min(G - 1, max(0, (int)((py - LOB) * INVH)));
    int cz = min(G - 1, max(0, (int)((pz - LOB) * INVH)));
    int c = slot * NC + ((cz * G + cy) * G + cx);
    g_pk[t] = make_float4(px, py, pz, 0.0f);
    g_cell[t] = c;
    atomicAdd(&g_cnt[c], 1);
}

// ---- 3-phase exclusive scan of g_cnt (524288 = 512 blocks x 1024) ---------
__global__ void scan1_kernel() {
    __shared__ int s[1024];
    int tid = threadIdx.x, i = blockIdx.x * 1024 + tid;
    int v = g_cnt[i];
    s[tid] = v;
    __syncthreads();
    #pragma unroll
    for (int o = 1; o < 1024; o <<= 1) {
        int a = (tid >= o) ? s[tid - o] : 0;
        __syncthreads();
        s[tid] += a;
        __syncthreads();
    }
    g_start[i] = s[tid] - v;                     // exclusive
    if (tid == 1023) g_bsum[blockIdx.x] = s[tid];
}

__global__ void scan2_kernel() {
    __shared__ int s[512];
    int tid = threadIdx.x;
    s[tid] = g_bsum[tid];
    __syncthreads();
    #pragma unroll
    for (int o = 1; o < 512; o <<= 1) {
        int a = (tid >= o) ? s[tid - o] : 0;
        __syncthreads();
        s[tid] += a;
        __syncthreads();
    }
    g_boff[tid] = (tid == 0) ? 0 : s[tid - 1];   // exclusive
    if (tid == 0) g_start[NCT] = TOTPTS;         // sentinel
}

__global__ void scan3_kernel() {
    int i = blockIdx.x * 1024 + threadIdx.x;
    int v = g_start[i] + g_boff[blockIdx.x];
    g_start[i] = v;
    g_cursor[i] = v;
}

__global__ void scatter_kernel() {
    int t = blockIdx.x * 256 + threadIdx.x;
    int pos = atomicAdd(&g_cursor[g_cell[t]], 1);
    g_sorted[pos] = g_pk[t];
}

// ---------------------------------------------------------------------------
__device__ __forceinline__ void scan_cells(int c0, int width, float4 qp,
                                           float& best) {
    int s = g_start[c0];
    int e = g_start[c0 + width];
    for (int j = s; j < e; j++) {
        float4 p = g_sorted[j];
        float dx = qp.x - p.x, dy = qp.y - p.y, dz = qp.z - p.z;
        float d2 = fmaf(dx, dx, fmaf(dy, dy, dz * dz));
        best = fminf(best, d2);
    }
}

// Exact NN via expanding Chebyshev shells. After ball r is scanned, any
// unscanned point is >= r*HCELL away (per-axis clamping is 1-Lipschitz, so
// the bound holds for clamped cell assignment too). Stop when best <= (r*h)^2.
__global__ void __launch_bounds__(256) query_kernel() {
    int qid = blockIdx.x * 256 + threadIdx.x;    // [0, 131072)
    int d = qid >> 16;                           // direction
    int q = qid & 65535;
    int b = q >> 13;
    int i = q & (NPTS - 1);
    int qslot  = b * 2 + d;                      // d0: query=x ; d1: query=y
    int dbslot = b * 2 + (1 - d);

    float4 qp = g_pk[qslot * NPTS + i];
    int cx = min(G - 1, max(0, (int)((qp.x - LOB) * INVH)));
    int cy = min(G - 1, max(0, (int)((qp.y - LOB) * INVH)));
    int cz = min(G - 1, max(0, (int)((qp.z - LOB) * INVH)));
    const int base = dbslot * NC;

    float best = 1e30f;

    // Ball r=1 (27 cells, 9 contiguous x-rows)
    for (int dz = -1; dz <= 1; dz++) {
        int z = cz + dz;
        if ((unsigned)z >= G) continue;
        for (int dy = -1; dy <= 1; dy++) {
            int y = cy + dy;
            if ((unsigned)y >= G) continue;
            int x0 = max(cx - 1, 0), x1 = min(cx + 1, G - 1);
            scan_cells(base + (z * G + y) * G + x0, x1 - x0 + 1, qp, best);
        }
    }

    int r = 1;
    while (!(best <= (r * HCELL) * (r * HCELL) * 0.9999f) && r < G) {
        r++;
        // shell at Chebyshev distance exactly r
        for (int dz = -r; dz <= r; dz++) {
            int z = cz + dz;
            if ((unsigned)z >= G) continue;
            int adz = (dz < 0) ? -dz : dz;
            for (int dy = -r; dy <= r; dy++) {
                int y = cy + dy;
                if ((unsigned)y >= G) continue;
                int ady = (dy < 0) ? -dy : dy;
                int rowbase = base + (z * G + y) * G;
                if (adz == r || ady == r) {
                    int x0 = max(cx - r, 0), x1 = min(cx + r, G - 1);
                    scan_cells(rowbase + x0, x1 - x0 + 1, qp, best);
                } else {
                    int xa = cx - r;
                    if (xa >= 0) scan_cells(rowbase + xa, 1, qp, best);
                    int xb = cx + r;
                    if (xb < G) scan_cells(rowbase + xb, 1, qp, best);
                }
            }
        }
    }

    float dist = sqrtf(best + EPSF);

    __shared__ float red[256];
    int tid = threadIdx.x;
    red[tid] = dist;
    __syncthreads();
    #pragma unroll
    for (int s = 128; s > 0; s >>= 1) {
        if (tid < s) red[tid] += red[tid + s];
        __syncthreads();
    }
    if (tid == 0) g_part[blockIdx.x] = red[0];
}

// Fold 512 partials -> per-(dir,batch) sums -> max -> mean -> total.
// Query block layout: blk = d*256 + b*32 + k, k in [0,32).
__global__ void __launch_bounds__(512) final_kernel(float* __restrict__ out) {
    int w = threadIdx.x >> 5, lane = threadIdx.x & 31;   // 16 warps = (d,b)
    int d = w >> 3, b = w & 7;
    float s = g_part[d * 256 + b * 32 + lane];
    #pragma unroll
    for (int o = 16; o > 0; o >>= 1)
        s += __shfl_down_sync(0xffffffffu, s, o);
    __shared__ float ss[16];
    if (lane == 0) ss[w] = s;
    __syncthreads();
    if (threadIdx.x == 0) {
        float tot = 0.0f;
        #pragma unroll
        for (int bb = 0; bb < BATCH; bb++)
            tot += fmaxf(ss[bb], ss[8 + bb]) * (1.0f / NPTS);
        out[0] = tot;
    }
}

// ---------------------------------------------------------------------------
extern "C" void kernel_launch(void* const* d_in, const int* in_sizes, int n_in,
                              void* d_out, int out_size) {
    const float* x = (const float*)d_in[0];
    const float* y = (const float*)d_in[1];
    float* out = (float*)d_out;

    zero_kernel<<<512, 1024>>>();
    assign_kernel<<<TOTPTS / 256, 256>>>(x, y);
    scan1_kernel<<<512, 1024>>>();
    scan2_kernel<<<1, 512>>>();
    scan3_kernel<<<512, 1024>>>();
    scatter_kernel<<<TOTPTS / 256, 256>>>();
    query_kernel<<<512, 256>>>();
    final_kernel<<<1, 512>>>(out);
}

// round 4
// speedup vs baseline: 2.3279x; 1.4320x over previous
#include <cuda_runtime.h>
#include <math.h>

#define BATCH 8
#define NPTS  8192
#define NSLOT 16                     // 8 batches x 2 clouds
#define TOTPTS (NSLOT * NPTS)        // 131072
#define G 32
#define NC (G * G * G)               // 32768 cells per grid
#define NCT (NSLOT * NC)             // 524288 cells total
#define LOB  (-5.5f)
#define HCELL (11.0f / G)
#define INVH  (G / 11.0f)
#define EPSF 1e-10f

// ---- static scratch (no allocation allowed) -------------------------------
__device__ float4 g_pk[TOTPTS];      // packed points, original order
__device__ float4 g_sorted[TOTPTS];  // points sorted by cell (global CSR)
__device__ int    g_cell[TOTPTS];    // flat cell id per point
__device__ int    g_cnt[NCT];        // per-cell counts
__device__ int    g_start[NCT + 1];  // CSR starts (exclusive scan) + sentinel
__device__ int    g_cursor[NCT];     // scatter cursors
__device__ int    g_bsum[512];
__device__ int    g_boff[512];
__device__ float  g_part[512];       // per-block partial sums of sqrt(min)

// ---------------------------------------------------------------------------
__global__ void zero_kernel() {     // 524288 ints = 131072 int4 stores
    int i = blockIdx.x * 1024 + threadIdx.x;
    ((int4*)g_cnt)[i] = make_int4(0, 0, 0, 0);
}

// Pack points, compute cells, histogram.
// t in [0,131072): slot = t>>13 (b*2 + side), i = t&8191. side0=x, side1=y.
__global__ void assign_kernel(const float* __restrict__ x,
                              const float* __restrict__ y) {
    int t = blockIdx.x * 256 + threadIdx.x;
    int slot = t >> 13, i = t & (NPTS - 1);
    int b = slot >> 1;
    const float* src = (slot & 1) ? y : x;
    const float* p = src + ((size_t)b * NPTS + i) * 3;
    float px = p[0], py = p[1], pz = p[2];
    int cx = min(G - 1, max(0, (int)((px - LOB) * INVH)));
    int cy = min(G - 1, max(0, (int)((py - LOB) * INVH)));
    int cz = min(G - 1, max(0, (int)((pz - LOB) * INVH)));
    int c = slot * NC + ((cz * G + cy) * G + cx);
    g_pk[t] = make_float4(px, py, pz, 0.0f);
    g_cell[t] = c;
    atomicAdd(&g_cnt[c], 1);
}

// ---- 3-phase exclusive scan of g_cnt (shuffle-based) ----------------------
__global__ void scan1_kernel() {
    int tid = threadIdx.x, i = blockIdx.x * 1024 + tid;
    int lane = tid & 31, w = tid >> 5;
    int v = g_cnt[i];
    int s = v;                                    // inclusive warp scan
    #pragma unroll
    for (int o = 1; o < 32; o <<= 1) {
        int t = __shfl_up_sync(0xffffffffu, s, o);
        if (lane >= o) s += t;
    }
    __shared__ int ws[32];
    if (lane == 31) ws[w] = s;
    __syncthreads();
    if (w == 0) {
        int t = ws[lane];
        #pragma unroll
        for (int o = 1; o < 32; o <<= 1) {
            int u = __shfl_up_sync(0xffffffffu, t, o);
            if (lane >= o) t += u;
        }
        ws[lane] = t;                             // inclusive warp-sum scan
    }
    __syncthreads();
    int off = (w > 0) ? ws[w - 1] : 0;
    g_start[i] = off + s - v;                     // exclusive within block
    if (tid == 1023) g_bsum[blockIdx.x] = ws[31];
}

__global__ void scan2_kernel() {                  // 512 values, 16 warps
    int tid = threadIdx.x, lane = tid & 31, w = tid >> 5;
    int v = g_bsum[tid];
    int s = v;
    #pragma unroll
    for (int o = 1; o < 32; o <<= 1) {
        int t = __shfl_up_sync(0xffffffffu, s, o);
        if (lane >= o) s += t;
    }
    __shared__ int ws[16];
    if (lane == 31) ws[w] = s;
    __syncthreads();
    if (w == 0 && lane < 16) {
        int t = ws[lane];
        #pragma unroll
        for (int o = 1; o < 16; o <<= 1) {
            int u = __shfl_up_sync(0xffffu, t, o);
            if (lane >= o) t += u;
        }
        ws[lane] = t;
    }
    __syncthreads();
    int off = (w > 0) ? ws[w - 1] : 0;
    g_boff[tid] = off + s - v;                    // exclusive
    if (tid == 0) g_start[NCT] = TOTPTS;          // sentinel
}

__global__ void scan3_kernel() {
    int i = blockIdx.x * 1024 + threadIdx.x;
    int v = g_start[i] + g_boff[blockIdx.x];
    g_start[i] = v;
    g_cursor[i] = v;
}

__global__ void scatter_kernel() {
    int t = blockIdx.x * 256 + threadIdx.x;
    int pos = atomicAdd(&g_cursor[g_cell[t]], 1);
    g_sorted[pos] = g_pk[t];
}

// ---------------------------------------------------------------------------
__device__ __forceinline__ void scan_cells(int c0, int width, float4 qp,
                                           float& best) {
    int s = g_start[c0];
    int e = g_start[c0 + width];
    for (int j = s; j < e; j++) {
        float4 p = g_sorted[j];
        float dx = qp.x - p.x, dy = qp.y - p.y, dz = qp.z - p.z;
        float d2 = fmaf(dx, dx, fmaf(dy, dy, dz * dz));
        best = fminf(best, d2);
    }
}

// Exact NN via expanding Chebyshev shells, querying in CELL-SORTED order:
// the 32 lanes of a warp hold spatially adjacent queries -> near-identical
// scan ranges (broadcast loads) and near-identical shell radii. Sum of
// sqrt(min) is order-independent, so sorted order needs no un-permutation.
// Correctness: after ball r is scanned, any unscanned point is >= r*HCELL
// away (per-axis clamped assignment is 1-Lipschitz), stop when
// best <= (r*h)^2; r reaches G in the worst case => full scan => exact.
__global__ void __launch_bounds__(256) query_kernel() {
    int qid = blockIdx.x * 256 + threadIdx.x;    // [0, 131072)
    int d = qid >> 16;                           // direction
    int q = qid & 65535;
    int b = q >> 13;                             // batch
    int i = q & (NPTS - 1);                      // sorted index within slot
    int qslot  = b * 2 + d;                      // d0: query cloud = x
    int dbslot = b * 2 + (1 - d);                // database = other cloud

    float4 qp = g_sorted[qslot * NPTS + i];      // CELL-SORTED query
    int cx = min(G - 1, max(0, (int)((qp.x - LOB) * INVH)));
    int cy = min(G - 1, max(0, (int)((qp.y - LOB) * INVH)));
    int cz = min(G - 1, max(0, (int)((qp.z - LOB) * INVH)));
    const int base = dbslot * NC;

    float best = 1e30f;

    // Ball r=1 (27 cells as 9 contiguous x-rows)
    for (int dz = -1; dz <= 1; dz++) {
        int z = cz + dz;
        if ((unsigned)z >= G) continue;
        for (int dy = -1; dy <= 1; dy++) {
            int y = cy + dy;
            if ((unsigned)y >= G) continue;
            int x0 = max(cx - 1, 0), x1 = min(cx + 1, G - 1);
            scan_cells(base + (z * G + y) * G + x0, x1 - x0 + 1, qp, best);
        }
    }

    int r = 1;
    while (!(best <= (r * HCELL) * (r * HCELL) * 0.9999f) && r < G) {
        r++;
        for (int dz = -r; dz <= r; dz++) {       // shell at Chebyshev dist r
            int z = cz + dz;
            if ((unsigned)z >= G) continue;
            int adz = (dz < 0) ? -dz : dz;
            for (int dy = -r; dy <= r; dy++) {
                int y = cy + dy;
                if ((unsigned)y >= G) continue;
                int ady = (dy < 0) ? -dy : dy;
                int rowbase = base + (z * G + y) * G;
                if (adz == r || ady == r) {
                    int x0 = max(cx - r, 0), x1 = min(cx + r, G - 1);
                    scan_cells(rowbase + x0, x1 - x0 + 1, qp, best);
                } else {
                    int xa = cx - r;
                    if (xa >= 0) scan_cells(rowbase + xa, 1, qp, best);
                    int xb = cx + r;
                    if (xb < G) scan_cells(rowbase + xb, 1, qp, best);
                }
            }
        }
    }

    float dist = sqrtf(best + EPSF);

    __shared__ float red[256];
    int tid = threadIdx.x;
    red[tid] = dist;
    __syncthreads();
    #pragma unroll
    for (int s = 128; s > 0; s >>= 1) {
        if (tid < s) red[tid] += red[tid + s];
        __syncthreads();
    }
    if (tid == 0) g_part[blockIdx.x] = red[0];
}

// Fold 512 partials -> per-(dir,batch) sums -> max -> mean -> total.
// Query block layout: blk = d*256 + b*32 + k, k in [0,32).
__global__ void __launch_bounds__(512) final_kernel(float* __restrict__ out) {
    int w = threadIdx.x >> 5, lane = threadIdx.x & 31;   // 16 warps = (d,b)
    int d = w >> 3, b = w & 7;
    float s = g_part[d * 256 + b * 32 + lane];
    #pragma unroll
    for (int o = 16; o > 0; o >>= 1)
        s += __shfl_down_sync(0xffffffffu, s, o);
    __shared__ float ss[16];
    if (lane == 0) ss[w] = s;
    __syncthreads();
    if (threadIdx.x == 0) {
        float tot = 0.0f;
        #pragma unroll
        for (int bb = 0; bb < BATCH; bb++)
            tot += fmaxf(ss[bb], ss[8 + bb]) * (1.0f / NPTS);
        out[0] = tot;
    }
}

// ---------------------------------------------------------------------------
extern "C" void kernel_launch(void* const* d_in, const int* in_sizes, int n_in,
                              void* d_out, int out_size) {
    const float* x = (const float*)d_in[0];
    const float* y = (const float*)d_in[1];
    float* out = (float*)d_out;

    zero_kernel<<<128, 1024>>>();
    assign_kernel<<<TOTPTS / 256, 256>>>(x, y);
    scan1_kernel<<<512, 1024>>>();
    scan2_kernel<<<1, 512>>>();
    scan3_kernel<<<512, 1024>>>();
    scatter_kernel<<<TOTPTS / 256, 256>>>();
    query_kernel<<<512, 256>>>();
    final_kernel<<<1, 512>>>(out);
}